// round 13
// baseline (speedup 1.0000x reference)
#include <cuda_runtime.h>
#include <cstdint>

// CombineEmbeddings: out[b,s,:] = (idx[b,s] >= 0) ? patch[b, idx[b,s], :]
//                                                 : word[b, s, :]
// Shapes (fixed for this problem): B=4, S=4096, P=2048, H=4096, fp32.
//
// FINAL. Pure HBM-bound row copy at the traffic floor (256 MiB read +
// 256 MiB write; zero reuse is structural). Runs at 6.33-6.42 TB/s
// (~80% DRAM-active), empirically established as this part's ceiling for
// a 1:1 interleaved read/write streaming mix by a complete sweep:
//   data path    : LDG/STG == 256-bit == cp.async.bulk (UBLKCP) — all
//                  79.9-81.1% DRAM; driver memcpy slower (serialized).
//                  Burst shape proven irrelevant (16KB bulk txns == 128B
//                  warp requests).
//   per-warp MLP : depth 2 / 4 / 8 -> 70.5 / 80.9 / 79.9% (saturates at 4)
//   rows per CTA : 1 best; 2-row and 8-row-pipelined regress (L1tex queue)
//   cache hints  : .nc / .cs neutral (no reuse either way)
// Issue% ~4, all compute pipes ~0: SMs idle, DRAM binding. Done.
//
// Shape: one CTA per 16 KB row (16384 micro-CTAs), 256 threads,
// 4 front-batched float4 loads -> 4 stores, source pointer selected once
// per CTA (uniform branch, no divergence). 26 regs, occ ~86%.

#define CE_B 4
#define CE_S 4096
#define CE_P 2048
#define CE_H 4096

__global__ void __launch_bounds__(256)
combine_embeddings_kernel(const float4* __restrict__ word,
                          const float4* __restrict__ patch,
                          const int*    __restrict__ idx,
                          float4*       __restrict__ out)
{
    constexpr int H4 = CE_H / 4;             // 1024 float4 per row
    const int row = blockIdx.x;              // 0 .. B*S-1
    const int b   = row >> 12;               // row / S  (S = 4096)
    const int i   = __ldg(idx + row);

    const float4* __restrict__ src =
        (i >= 0) ? (patch + ((int64_t)b * CE_P + i) * H4)
                 : (word  + (int64_t)row * H4);
    float4* __restrict__ dst = out + (int64_t)row * H4;

    // 1024 float4 / 256 threads = 4 iterations, fully unrolled:
    // all 4 loads (64 B/thread) in flight before the first store binds.
    const int t = threadIdx.x;
    float4 v0 = src[t];
    float4 v1 = src[t + 256];
    float4 v2 = src[t + 512];
    float4 v3 = src[t + 768];
    dst[t]       = v0;
    dst[t + 256] = v1;
    dst[t + 512] = v2;
    dst[t + 768] = v3;
}

extern "C" void kernel_launch(void* const* d_in, const int* in_sizes, int n_in,
                              void* d_out, int out_size)
{
    const float4* word  = (const float4*)d_in[0];   // [B, S, H] fp32
    const float4* patch = (const float4*)d_in[1];   // [B, P, H] fp32
    const int*    idx   = (const int*)d_in[2];      // [B, S] int32
    float4*       out   = (float4*)d_out;           // [B, S, H] fp32

    const int rows = CE_B * CE_S;                   // 16384
    combine_embeddings_kernel<<<rows, 256>>>(word, patch, idx, out);
}

// round 14
// speedup vs baseline: 1.0082x; 1.0082x over previous
#include <cuda_runtime.h>
#include <cstdint>

// CombineEmbeddings: out[b,s,:] = (idx[b,s] >= 0) ? patch[b, idx[b,s], :]
//                                                 : word[b, s, :]
// Shapes (fixed for this problem): B=4, S=4096, P=2048, H=4096, fp32.
//
// FINAL — CONVERGED. Pure HBM-bound row copy at the traffic floor
// (256 MiB read + 256 MiB write; zero reuse is structural). Runs at
// 6.33-6.42 TB/s (~80% DRAM-active), the empirically established ceiling
// for a 1:1 interleaved read/write streaming mix on this part:
//   data path    : LDG.128 == LDG.256 == cp.async.bulk (UBLKCP), all
//                  79.9-81.1% DRAM; driver memcpy slower (serialized CE).
//                  Burst shape irrelevant (16KB bulk txn == 128B requests).
//   per-warp MLP : depth 2 / 4 / 8 -> 70.5 / 80.9 / 79.9% (saturates at 4)
//   rows per CTA : 1 best; 2-row and 8-row-pipelined regress (L1tex queue)
//   cache hints  : .nc / .cs neutral;  occupancy: 19% == 86% at same DRAM%
// Issue% ~4, compute pipes ~0 in every run: SMs idle, DRAM binding.
// Six runs of this exact binary: 82.30-82.69us (noise band).
//
// Shape: one CTA per 16 KB row (16384 micro-CTAs), 256 threads,
// 4 front-batched float4 loads -> 4 stores, source pointer selected once
// per CTA (uniform branch, no divergence). 26 regs, occ ~84-86%.

#define CE_B 4
#define CE_S 4096
#define CE_P 2048
#define CE_H 4096

__global__ void __launch_bounds__(256)
combine_embeddings_kernel(const float4* __restrict__ word,
                          const float4* __restrict__ patch,
                          const int*    __restrict__ idx,
                          float4*       __restrict__ out)
{
    constexpr int H4 = CE_H / 4;             // 1024 float4 per row
    const int row = blockIdx.x;              // 0 .. B*S-1
    const int b   = row >> 12;               // row / S  (S = 4096)
    const int i   = __ldg(idx + row);

    const float4* __restrict__ src =
        (i >= 0) ? (patch + ((int64_t)b * CE_P + i) * H4)
                 : (word  + (int64_t)row * H4);
    float4* __restrict__ dst = out + (int64_t)row * H4;

    // 1024 float4 / 256 threads = 4 iterations, fully unrolled:
    // all 4 loads (64 B/thread) in flight before the first store binds.
    const int t = threadIdx.x;
    float4 v0 = src[t];
    float4 v1 = src[t + 256];
    float4 v2 = src[t + 512];
    float4 v3 = src[t + 768];
    dst[t]       = v0;
    dst[t + 256] = v1;
    dst[t + 512] = v2;
    dst[t + 768] = v3;
}

extern "C" void kernel_launch(void* const* d_in, const int* in_sizes, int n_in,
                              void* d_out, int out_size)
{
    const float4* word  = (const float4*)d_in[0];   // [B, S, H] fp32
    const float4* patch = (const float4*)d_in[1];   // [B, P, H] fp32
    const int*    idx   = (const int*)d_in[2];      // [B, S] int32
    float4*       out   = (float4*)d_out;           // [B, S, H] fp32

    const int rows = CE_B * CE_S;                   // 16384
    combine_embeddings_kernel<<<rows, 256>>>(word, patch, idx, out);
}